// round 5
// baseline (speedup 1.0000x reference)
#include <cuda_runtime.h>
#include <cuda_bf16.h>
#include <cstdint>

#define Bb 4
#define Hh 16
#define Ss 2048
#define Dd 64
#define BH (Bb*Hh)
#define CTX_ELEMS ((size_t)Bb*Hh*Ss*Dd)      // 8388608

// ---------------------------------------------------------------------------
// Scratch (allocation-free rule: __device__ globals)
// ---------------------------------------------------------------------------
__device__ __nv_bfloat16 g_Qhi[(size_t)BH*Ss*Dd];
__device__ __nv_bfloat16 g_Qlo[(size_t)BH*Ss*Dd];
__device__ __nv_bfloat16 g_Khi[(size_t)BH*Ss*Dd];
__device__ __nv_bfloat16 g_Klo[(size_t)BH*Ss*Dd];
__device__ __nv_bfloat16 g_Vthi[(size_t)BH*Dd*Ss];   // [bh][d][k]
__device__ __nv_bfloat16 g_Vtlo[(size_t)BH*Dd*Ss];
__device__ float g_M[(size_t)BH*Ss];                 // row max of scores
__device__ float g_Z[(size_t)BH*Ss];                 // row sum of exp(s-M)

// ---------------------------------------------------------------------------
// Helpers
// ---------------------------------------------------------------------------
__device__ __forceinline__ uint32_t smem_u32(const void* p) {
    uint32_t a;
    asm("{ .reg .u64 t; cvta.to.shared.u64 t, %1; cvt.u32.u64 %0, t; }" : "=r"(a) : "l"(p));
    return a;
}
__device__ __forceinline__ uint32_t pack2(float a, float b) {
    __nv_bfloat162 t;
    t.x = __float2bfloat16(a);
    t.y = __float2bfloat16(b);
    return *(uint32_t*)&t;
}
__device__ __forceinline__ uint32_t sw_addr(uint32_t base, int row, int kbyte) {
    return base + row * 128 + (kbyte ^ ((row & 7) << 4));
}
__device__ __forceinline__ void ldsm4(uint32_t r[4], uint32_t addr) {
    asm volatile("ldmatrix.sync.aligned.m8n8.x4.shared.b16 {%0,%1,%2,%3}, [%4];"
        : "=r"(r[0]), "=r"(r[1]), "=r"(r[2]), "=r"(r[3]) : "r"(addr));
}
__device__ __forceinline__ void mma16816(float c[4], const uint32_t a[4], const uint32_t b[2]) {
    asm volatile("mma.sync.aligned.m16n8k16.row.col.f32.bf16.bf16.f32 "
        "{%0,%1,%2,%3}, {%4,%5,%6,%7}, {%8,%9}, {%0,%1,%2,%3};"
        : "+f"(c[0]), "+f"(c[1]), "+f"(c[2]), "+f"(c[3])
        : "r"(a[0]), "r"(a[1]), "r"(a[2]), "r"(a[3]), "r"(b[0]), "r"(b[1]));
}

// ---------------------------------------------------------------------------
// Prep 1: fp32 -> (hi, lo) bf16 split, same layout.
// ---------------------------------------------------------------------------
__global__ void conv_split(const float* __restrict__ src,
                           __nv_bfloat16* __restrict__ hi,
                           __nv_bfloat16* __restrict__ lo) {
    size_t i = ((size_t)blockIdx.x * blockDim.x + threadIdx.x) * 4;
    float4 v = *(const float4*)(src + i);
    float f[4] = {v.x, v.y, v.z, v.w};
    float r[4];
    __nv_bfloat16 hb[4];
    #pragma unroll
    for (int j = 0; j < 4; j++) { hb[j] = __float2bfloat16(f[j]); r[j] = f[j] - __bfloat162float(hb[j]); }
    uint32_t h0 = pack2(__bfloat162float(hb[0]), __bfloat162float(hb[1]));
    uint32_t h1 = pack2(__bfloat162float(hb[2]), __bfloat162float(hb[3]));
    uint32_t l0 = pack2(r[0], r[1]);
    uint32_t l1 = pack2(r[2], r[3]);
    *(uint2*)(hi + i) = make_uint2(h0, h1);
    *(uint2*)(lo + i) = make_uint2(l0, l1);
}

// ---------------------------------------------------------------------------
// Prep 2: V [bh][k][d] fp32 -> Vt hi/lo [bh][d][k] bf16.
// ---------------------------------------------------------------------------
__global__ void transpose_v(const float* __restrict__ v) {
    __shared__ float Vs[64][68];
    const int bh = blockIdx.y;
    const int k0 = blockIdx.x * 64;
    const int t = threadIdx.x;     // 256

    #pragma unroll
    for (int p = 0; p < 4; p++) {
        int lin = t + 256 * p;
        int r = lin >> 4, g4 = lin & 15;
        float4 a = *(const float4*)(v + ((size_t)bh * Ss + k0 + r) * Dd + g4 * 4);
        Vs[r][g4 * 4 + 0] = a.x; Vs[r][g4 * 4 + 1] = a.y;
        Vs[r][g4 * 4 + 2] = a.z; Vs[r][g4 * 4 + 3] = a.w;
    }
    __syncthreads();

    #pragma unroll
    for (int p = 0; p < 2; p++) {
        int lin = t + 256 * p;
        int d = lin >> 3, kg = lin & 7;
        uint32_t hw[4], lw[4];
        #pragma unroll
        for (int j = 0; j < 4; j++) {
            float a = Vs[kg * 8 + j * 2][d];
            float b = Vs[kg * 8 + j * 2 + 1][d];
            __nv_bfloat16 ha = __float2bfloat16(a), hb = __float2bfloat16(b);
            hw[j] = pack2(__bfloat162float(ha), __bfloat162float(hb));
            lw[j] = pack2(a - __bfloat162float(ha), b - __bfloat162float(hb));
        }
        size_t o = ((size_t)bh * Dd + d) * Ss + k0 + kg * 8;
        *(uint4*)(g_Vthi + o) = make_uint4(hw[0], hw[1], hw[2], hw[3]);
        *(uint4*)(g_Vtlo + o) = make_uint4(lw[0], lw[1], lw[2], lw[3]);
    }
}

// ---------------------------------------------------------------------------
// Kernel 1: scores + online softmax stats.  Block = (q-tile 128, bh), loops
// all 16 k-tiles. Writes raw scores to attn; final per-row (M, Z) to global.
// ---------------------------------------------------------------------------
#define SC_OFF_MASK  0                          // 2048 floats
#define SC_OFF_SM    8192                       // 128 floats
#define SC_OFF_SZ    8704                       // 128 floats
#define SC_OFF_PART  9216                       // float2 [2][128]
#define SC_OFF_QHI   11264
#define SC_OFF_QLO   (SC_OFF_QHI + 16384)
#define SC_OFF_KHI   (SC_OFF_QLO + 16384)
#define SC_OFF_KLO   (SC_OFF_KHI + 16384)
#define SC_SMEM      (SC_OFF_KLO + 16384)       // 76800

__global__ void __launch_bounds__(256, 2)
sdpa_scores_mma(const float* __restrict__ mask, float* __restrict__ attn) {
    extern __shared__ char smem[];
    const uint32_t sb = smem_u32(smem);
    const int t = threadIdx.x, lane = t & 31, w = t >> 5;
    const int q0 = blockIdx.x * 128;
    const int bh = blockIdx.y, b = bh / Hh;

    float*  mask_s = (float*)(smem + SC_OFF_MASK);
    float*  sM     = (float*)(smem + SC_OFF_SM);
    float*  sZ     = (float*)(smem + SC_OFF_SZ);
    float2* part   = (float2*)(smem + SC_OFF_PART);

    // ---- stage Q tiles (hi/lo) once, mask row, init stats ----
    {
        const char* qh = (const char*)(g_Qhi + (size_t)(bh * Ss + q0) * Dd);
        const char* ql = (const char*)(g_Qlo + (size_t)(bh * Ss + q0) * Dd);
        #pragma unroll
        for (int p = 0; p < 4; p++) {
            int g = t + 256 * p;
            int r = g >> 3, x = (g & 7) * 16;
            uint32_t swo = r * 128 + (x ^ ((r & 7) << 4));
            *(uint4*)(smem + SC_OFF_QHI + swo) = *(const uint4*)(qh + r * 128 + x);
            *(uint4*)(smem + SC_OFF_QLO + swo) = *(const uint4*)(ql + r * 128 + x);
        }
        const float4* msrc = (const float4*)(mask + (size_t)b * Ss);
        ((float4*)mask_s)[t]       = msrc[t];
        ((float4*)mask_s)[t + 256] = msrc[t + 256];
        if (t < 128) { sM[t] = -1e30f; sZ[t] = 0.0f; }
    }

    const int wm = w >> 1, wn = w & 1;
    const int m_base = wm * 32, n_base = wn * 64;
    const uint32_t qh = sb + SC_OFF_QHI, ql = sb + SC_OFF_QLO;
    const uint32_t kh = sb + SC_OFF_KHI, kl = sb + SC_OFF_KLO;

    for (int kt = 0; kt < 16; kt++) {
        __syncthreads();   // protects K smem + part buffer from previous tile
        // ---- stage K tile (hi/lo) ----
        {
            const char* khs = (const char*)(g_Khi + (size_t)(bh * Ss + kt * 128) * Dd);
            const char* kls = (const char*)(g_Klo + (size_t)(bh * Ss + kt * 128) * Dd);
            #pragma unroll
            for (int p = 0; p < 4; p++) {
                int g = t + 256 * p;
                int r = g >> 3, x = (g & 7) * 16;
                uint32_t swo = r * 128 + (x ^ ((r & 7) << 4));
                *(uint4*)(smem + SC_OFF_KHI + swo) = *(const uint4*)(khs + r * 128 + x);
                *(uint4*)(smem + SC_OFF_KLO + swo) = *(const uint4*)(kls + r * 128 + x);
            }
        }
        __syncthreads();

        // ---- MMA 128x128 tile, bf16x3 ----
        float c[2][8][4];
        #pragma unroll
        for (int i = 0; i < 2; i++)
            #pragma unroll
            for (int j = 0; j < 8; j++)
                #pragma unroll
                for (int e = 0; e < 4; e++) c[i][j][e] = 0.0f;

        #pragma unroll
        for (int ks = 0; ks < 4; ks++) {
            const int ko = ks * 16;
            uint32_t AH[2][4], AL[2][4];
            #pragma unroll
            for (int mf = 0; mf < 2; mf++) {
                int row = m_base + mf * 16 + (lane & 15);
                int kb = (ko + ((lane >> 4) << 3)) * 2;
                ldsm4(AH[mf], sw_addr(qh, row, kb));
                ldsm4(AL[mf], sw_addr(ql, row, kb));
            }
            #pragma unroll
            for (int np = 0; np < 4; np++) {
                int row = n_base + np * 16 + (lane & 7) + ((lane >> 4) << 3);
                int kb = (ko + (((lane >> 3) & 1) << 3)) * 2;
                uint32_t BH4[4], BL4[4];
                ldsm4(BH4, sw_addr(kh, row, kb));
                ldsm4(BL4, sw_addr(kl, row, kb));
                #pragma unroll
                for (int h = 0; h < 2; h++) {
                    const uint32_t bhr[2] = {BH4[2 * h], BH4[2 * h + 1]};
                    const uint32_t blr[2] = {BL4[2 * h], BL4[2 * h + 1]};
                    #pragma unroll
                    for (int mf = 0; mf < 2; mf++) {
                        mma16816(c[mf][2 * np + h], AH[mf], bhr);
                        mma16816(c[mf][2 * np + h], AH[mf], blr);
                        mma16816(c[mf][2 * np + h], AL[mf], bhr);
                    }
                }
            }
        }

        // ---- epilogue: scale+mask, write raw scores, per-row tile stats ----
        const int k0 = kt * 128;
        #pragma unroll
        for (int mf = 0; mf < 2; mf++) {
            #pragma unroll
            for (int rr = 0; rr < 2; rr++) {
                const int rloc = m_base + mf * 16 + rr * 8 + (lane >> 2);
                float sv[16];
                float tm = -1e30f;
                #pragma unroll
                for (int nf = 0; nf < 8; nf++) {
                    int cl = n_base + nf * 8 + 2 * (lane & 3);
                    float s0 = c[mf][nf][rr * 2 + 0] * 0.125f + mask_s[k0 + cl];
                    float s1 = c[mf][nf][rr * 2 + 1] * 0.125f + mask_s[k0 + cl + 1];
                    *(float2*)(attn + ((size_t)bh * Ss + q0 + rloc) * Ss + k0 + cl) =
                        make_float2(s0, s1);
                    sv[2 * nf] = s0; sv[2 * nf + 1] = s1;
                    tm = fmaxf(tm, fmaxf(s0, s1));
                }
                tm = fmaxf(tm, __shfl_xor_sync(0xffffffffu, tm, 1));
                tm = fmaxf(tm, __shfl_xor_sync(0xffffffffu, tm, 2));
                float z = 0.0f;
                #pragma unroll
                for (int i = 0; i < 16; i++) z += __expf(sv[i] - tm);
                z += __shfl_xor_sync(0xffffffffu, z, 1);
                z += __shfl_xor_sync(0xffffffffu, z, 2);
                if ((lane & 3) == 0) part[wn * 128 + rloc] = make_float2(tm, z);
            }
        }
        __syncthreads();
        if (t < 128) {
            float2 p0 = part[t], p1 = part[128 + t];
            float mt = fmaxf(p0.x, p1.x);
            float zt = p0.y * __expf(p0.x - mt) + p1.y * __expf(p1.x - mt);
            float M = sM[t], Z = sZ[t];
            float mn = fmaxf(M, mt);
            sZ[t] = Z * __expf(M - mn) + zt * __expf(mt - mn);
            sM[t] = mn;
        }
    }
    __syncthreads();
    if (t < 128) {
        g_M[(size_t)bh * Ss + q0 + t] = sM[t];
        g_Z[(size_t)bh * Ss + q0 + t] = sZ[t];
    }
}

// ---------------------------------------------------------------------------
// Kernel 3: context + attn normalization.  Block = (q-tile 128, bh).
// Reads raw scores, writes p = exp(s-M)/Z back to attn, MMA p @ V -> ctx.
// ---------------------------------------------------------------------------
#define CT_OFF_AHI  0
#define CT_OFF_ALO  (CT_OFF_AHI + 16384)
#define CT_OFF_VHI  (CT_OFF_ALO + 16384)
#define CT_OFF_VLO  (CT_OFF_VHI + 8192)
#define CT_OFF_CM   (CT_OFF_VLO + 8192)      // 128 floats
#define CT_OFF_CZ   (CT_OFF_CM + 512)        // 128 floats (1/Z)
#define CT_SMEM     (CT_OFF_CZ + 512)        // 50176

__global__ void __launch_bounds__(256)
sdpa_context_mma(float* __restrict__ attn, float* __restrict__ ctx) {
    extern __shared__ char smem[];
    const uint32_t sb = smem_u32(smem);
    const int t = threadIdx.x, lane = t & 31, w = t >> 5;
    const int bh = blockIdx.y;
    const int q0 = blockIdx.x * 128;

    float* ab = attn + ((size_t)bh * Ss + q0) * Ss;
    const char* vhb = (const char*)(g_Vthi + (size_t)bh * Dd * Ss);
    const char* vlb = (const char*)(g_Vtlo + (size_t)bh * Dd * Ss);
    float* cMs = (float*)(smem + CT_OFF_CM);
    float* cZs = (float*)(smem + CT_OFF_CZ);

    if (t < 128) {
        cMs[t] = g_M[(size_t)bh * Ss + q0 + t];
        cZs[t] = 1.0f / g_Z[(size_t)bh * Ss + q0 + t];
    }

    const int wm = w >> 1, wn = w & 1;
    const int m_base = wm * 32, n_base = wn * 32;
    const uint32_t ah = sb + CT_OFF_AHI, al = sb + CT_OFF_ALO;
    const uint32_t vh = sb + CT_OFF_VHI, vl = sb + CT_OFF_VLO;

    float c[2][4][4];
    #pragma unroll
    for (int i = 0; i < 2; i++)
        #pragma unroll
        for (int j = 0; j < 4; j++)
            #pragma unroll
            for (int e = 0; e < 4; e++) c[i][j][e] = 0.0f;

    for (int ch = 0; ch < 32; ch++) {
        __syncthreads();    // stats staged / previous chunk's ldsm done

        // A chunk: normalize, write back, split to bf16 hi/lo
        #pragma unroll
        for (int p = 0; p < 8; p++) {
            int lin = t + 256 * p;
            int r = lin >> 4, g4 = lin & 15;
            float* ap = ab + (size_t)r * Ss + ch * 64 + g4 * 4;
            float4 a = *(const float4*)ap;
            float m = cMs[r], iz = cZs[r];
            a.x = __expf(a.x - m) * iz;
            a.y = __expf(a.y - m) * iz;
            a.z = __expf(a.z - m) * iz;
            a.w = __expf(a.w - m) * iz;
            *(float4*)ap = a;   // normalized attention output
            __nv_bfloat16 h0 = __float2bfloat16(a.x), h1 = __float2bfloat16(a.y);
            __nv_bfloat16 h2 = __float2bfloat16(a.z), h3 = __float2bfloat16(a.w);
            uint32_t hi0 = pack2(__bfloat162float(h0), __bfloat162float(h1));
            uint32_t hi1 = pack2(__bfloat162float(h2), __bfloat162float(h3));
            uint32_t lo0 = pack2(a.x - __bfloat162float(h0), a.y - __bfloat162float(h1));
            uint32_t lo1 = pack2(a.z - __bfloat162float(h2), a.w - __bfloat162float(h3));
            int x = g4 * 8;
            uint32_t swo = r * 128 + (x ^ ((r & 7) << 4));
            *(uint2*)(smem + CT_OFF_AHI + swo) = make_uint2(hi0, hi1);
            *(uint2*)(smem + CT_OFF_ALO + swo) = make_uint2(lo0, lo1);
        }
        // V chunk
        #pragma unroll
        for (int p = 0; p < 2; p++) {
            int g = t + 256 * p;
            int r = g >> 3, x = (g & 7) * 16;
            uint4 dh = *(const uint4*)(vhb + (size_t)r * (Ss * 2) + ch * 128 + x);
            uint4 dl = *(const uint4*)(vlb + (size_t)r * (Ss * 2) + ch * 128 + x);
            uint32_t swo = r * 128 + (x ^ ((r & 7) << 4));
            *(uint4*)(smem + CT_OFF_VHI + swo) = dh;
            *(uint4*)(smem + CT_OFF_VLO + swo) = dl;
        }
        __syncthreads();

        #pragma unroll
        for (int ks = 0; ks < 4; ks++) {
            const int ko = ks * 16;
            uint32_t AH[2][4], AL[2][4];
            #pragma unroll
            for (int mf = 0; mf < 2; mf++) {
                int row = m_base + mf * 16 + (lane & 15);
                int kb = (ko + ((lane >> 4) << 3)) * 2;
                ldsm4(AH[mf], sw_addr(ah, row, kb));
                ldsm4(AL[mf], sw_addr(al, row, kb));
            }
            #pragma unroll
            for (int np = 0; np < 2; np++) {
                int row = n_base + np * 16 + (lane & 7) + ((lane >> 4) << 3);
                int kb = (ko + (((lane >> 3) & 1) << 3)) * 2;
                uint32_t BH4[4], BL4[4];
                ldsm4(BH4, sw_addr(vh, row, kb));
                ldsm4(BL4, sw_addr(vl, row, kb));
                #pragma unroll
                for (int h = 0; h < 2; h++) {
                    const uint32_t bhr[2] = {BH4[2 * h], BH4[2 * h + 1]};
                    const uint32_t blr[2] = {BL4[2 * h], BL4[2 * h + 1]};
                    #pragma unroll
                    for (int mf = 0; mf < 2; mf++) {
                        mma16816(c[mf][2 * np + h], AH[mf], bhr);
                        mma16816(c[mf][2 * np + h], AH[mf], blr);
                        mma16816(c[mf][2 * np + h], AL[mf], bhr);
                    }
                }
            }
        }
    }

    // ---- epilogue ----
    #pragma unroll
    for (int mf = 0; mf < 2; mf++) {
        int r0 = q0 + m_base + mf * 16 + (lane >> 2);
        #pragma unroll
        for (int nf = 0; nf < 4; nf++) {
            int col = n_base + nf * 8 + 2 * (lane & 3);
            float2 v0 = {c[mf][nf][0], c[mf][nf][1]};
            float2 v1 = {c[mf][nf][2], c[mf][nf][3]};
            *(float2*)(ctx + ((size_t)bh * Ss + r0) * Dd + col) = v0;
            *(float2*)(ctx + ((size_t)bh * Ss + r0 + 8) * Dd + col) = v1;
        }
    }
}

// ---------------------------------------------------------------------------
extern "C" void kernel_launch(void* const* d_in, const int* in_sizes, int n_in,
                              void* d_out, int out_size) {
    const float* q    = (const float*)d_in[0];
    const float* k    = (const float*)d_in[1];
    const float* v    = (const float*)d_in[2];
    const float* mask = (const float*)d_in[3];

    float* ctx  = (float*)d_out;
    float* attn = (float*)d_out + CTX_ELEMS;

    cudaFuncSetAttribute(sdpa_scores_mma,  cudaFuncAttributeMaxDynamicSharedMemorySize, SC_SMEM);
    cudaFuncSetAttribute(sdpa_context_mma, cudaFuncAttributeMaxDynamicSharedMemorySize, CT_SMEM);

    __nv_bfloat16 *qhi, *qlo, *khi, *klo;
    cudaGetSymbolAddress((void**)&qhi, g_Qhi);
    cudaGetSymbolAddress((void**)&qlo, g_Qlo);
    cudaGetSymbolAddress((void**)&khi, g_Khi);
    cudaGetSymbolAddress((void**)&klo, g_Klo);

    const size_t nf4 = (size_t)BH * Ss * Dd / 4;
    conv_split<<<nf4 / 256, 256>>>(q, qhi, qlo);
    conv_split<<<nf4 / 256, 256>>>(k, khi, klo);
    transpose_v<<<dim3(Ss / 64, BH), 256>>>(v);

    sdpa_scores_mma<<<dim3(Ss / 128, BH), 256, SC_SMEM>>>(mask, attn);
    sdpa_context_mma<<<dim3(Ss / 128, BH), 256, CT_SMEM>>>(attn, ctx);
}